// round 7
// baseline (speedup 1.0000x reference)
#include <cuda_runtime.h>
#include <cstdint>

// Problem constants
#define BB    8
#define C     128
#define W     256
#define H     256
#define NPIX  (W*H)          // 65536 pixels per image
#define NBLK  512

// Output buffer layout (concatenated f32, raw reshapes):
#define OFF_CENTERS 0
#define OFF_LABELS  256
#define OFF_ONEHOT  (OFF_LABELS + BB*NPIX)
#define OFF_DIST    (OFF_ONEHOT + BB*2*NPIX)
#define OFF_LABELT  (OFF_DIST   + BB*2*NPIX)

// Scratch (__device__ globals). Zero at load; epilogue self-resets each run.
__device__ float g_sum[2*C];     // atomic per-(label,channel) sums, batch 7
__device__ int   g_cnt = 0;      // atomic label==1 count, batch 7
__device__ int   g_arrive = 0;   // arrival counter

// ---------------------------------------------------------------------------
// Single kernel, 512 blocks x 256 threads.
// Phase A : every block owns a 32-float4 (128-pixel, 64KB) chunk of batch 7.
//           8 threads/float4-pixel compute partial dots over 16 channels each,
//           xor-shuffle reduce, labels -> smem, outputs staged+written.
//           The 64KB tile lands in L1.
// Phase A2: masked per-channel sums over the SAME 64KB tile -> all L1 hits.
//           Warp w owns channels w+8k; lane = pixel-group. atomicAdd results.
// Phase B : blocks 0..447 stream batches 0..6 exactly like the proven
//           roofline pass (ldcs loads, stcs stores).
// Epilogue: last-arriving block computes centersIterout, resets scratch.
// No inter-block waits anywhere except the terminal arrival counter.
// ---------------------------------------------------------------------------
__global__ void __launch_bounds__(256, 4)
k_all(const float* __restrict__ F,
      const float* __restrict__ Cinit,
      float* __restrict__ out) {
    __shared__ float  sc[2*C];
    __shared__ float4 slab[32];     // labels per float4-pixel group
    __shared__ float4 sd0[32];      // d0 per group
    __shared__ float4 sd1[32];      // d1 per group
    __shared__ int    s_done;

    int t    = threadIdx.x;
    int lane = t & 31;
    int warp = t >> 5;
    int blk  = blockIdx.x;

    sc[t] = Cinit[t];
    __syncthreads();

    const float4* F7 = reinterpret_cast<const float4*>(F + (size_t)(BB-1) * C * NPIX);
    int base = blk * 32;                 // this block's float4-pixel chunk in b7

    // ---------------- Phase A: batch-7 chunk, 8 threads per float4-pixel ----
    {
        int g = t >> 3;                  // pixel group 0..31
        int s = t & 7;                   // sub-thread: channels s, s+8, ..., s+120
        int p4 = base + g;

        float a0x=0.f,a0y=0.f,a0z=0.f,a0w=0.f;
        float a1x=0.f,a1y=0.f,a1z=0.f,a1w=0.f;
        #pragma unroll
        for (int k = 0; k < 16; k++) {
            int ch = s + 8*k;
            float4 f = F7[ch * (NPIX/4) + p4];   // default policy -> L1-resident
            float c0 = sc[ch], c1 = sc[C + ch];
            a0x += f.x*c0; a0y += f.y*c0; a0z += f.z*c0; a0w += f.w*c0;
            a1x += f.x*c1; a1y += f.y*c1; a1z += f.z*c1; a1w += f.w*c1;
        }
        // reduce across the 8 subs (lanes differing in low 3 bits)
        #pragma unroll
        for (int o = 1; o <= 4; o <<= 1) {
            a0x += __shfl_xor_sync(0xffffffffu, a0x, o);
            a0y += __shfl_xor_sync(0xffffffffu, a0y, o);
            a0z += __shfl_xor_sync(0xffffffffu, a0z, o);
            a0w += __shfl_xor_sync(0xffffffffu, a0w, o);
            a1x += __shfl_xor_sync(0xffffffffu, a1x, o);
            a1y += __shfl_xor_sync(0xffffffffu, a1y, o);
            a1z += __shfl_xor_sync(0xffffffffu, a1z, o);
            a1w += __shfl_xor_sync(0xffffffffu, a1w, o);
        }
        if (s == 0) {
            float d0x = 0.5f - 0.5f*a0x, d1x = 0.5f - 0.5f*a1x;
            float d0y = 0.5f - 0.5f*a0y, d1y = 0.5f - 0.5f*a1y;
            float d0z = 0.5f - 0.5f*a0z, d1z = 0.5f - 0.5f*a1z;
            float d0w = 0.5f - 0.5f*a0w, d1w = 0.5f - 0.5f*a1w;
            slab[g] = make_float4((float)(d1x<d0x), (float)(d1y<d0y),
                                  (float)(d1z<d0z), (float)(d1w<d0w));
            sd0[g] = make_float4(d0x, d0y, d0z, d0w);
            sd1[g] = make_float4(d1x, d1y, d1z, d1w);
        }
    }
    __syncthreads();

    // ---- write b7 outputs from staged smem (coalesced runs) ----
    {
        float4* L4 = reinterpret_cast<float4*>(out + OFF_LABELS + (size_t)(BB-1)*NPIX);
        float4* T4 = reinterpret_cast<float4*>(out + OFF_LABELT + (size_t)(BB-1)*NPIX);
        float4* O4 = reinterpret_cast<float4*>(out + OFF_ONEHOT + (size_t)(BB-1)*2*NPIX);
        float4* D4 = reinterpret_cast<float4*>(out + OFF_DIST   + (size_t)(BB-1)*2*NPIX);
        if (t < 32) {
            __stcs(&L4[base + t], slab[t]);
        } else if (t < 64) {
            __stcs(&T4[base + (t-32)], slab[t-32]);
        } else if (t < 128) {
            int idx = t - 64, j = idx >> 1, h = idx & 1;
            float4 l = slab[j];
            float4 v = h ? make_float4(1.f-l.z, l.z, 1.f-l.w, l.w)
                         : make_float4(1.f-l.x, l.x, 1.f-l.y, l.y);
            __stcs(&O4[2*base + idx], v);
        } else if (t < 192) {
            int idx = t - 128, j = idx >> 1, h = idx & 1;
            float4 d0 = sd0[j], d1 = sd1[j];
            float4 v = h ? make_float4(d0.z, d1.z, d0.w, d1.w)
                         : make_float4(d0.x, d1.x, d0.y, d1.y);
            __stcs(&D4[2*base + idx], v);
        }
    }

    // ---- label-1 count for this chunk (warp 0) ----
    if (warp == 0) {
        float4 l = slab[lane];
        float c = l.x + l.y + l.z + l.w;
        #pragma unroll
        for (int o = 16; o > 0; o >>= 1)
            c += __shfl_down_sync(0xffffffffu, c, o);
        if (lane == 0) atomicAdd(&g_cnt, (int)c);
    }

    // ---------------- Phase A2: masked channel sums, all L1 hits ----------
    {
        float4 ml = slab[lane];          // labels of pixel-group 'lane'
        #pragma unroll
        for (int k = 0; k < 16; k++) {
            int ch = warp + 8*k;
            float4 f = F7[ch * (NPIX/4) + base + lane];   // L1 hit (phase-A tile)
            float sa = f.x + f.y + f.z + f.w;
            float s1 = f.x*ml.x + f.y*ml.y + f.z*ml.z + f.w*ml.w;
            #pragma unroll
            for (int o = 16; o > 0; o >>= 1) {
                sa += __shfl_down_sync(0xffffffffu, sa, o);
                s1 += __shfl_down_sync(0xffffffffu, s1, o);
            }
            if (lane == 0) {
                atomicAdd(&g_sum[ch],     sa - s1);   // label 0
                atomicAdd(&g_sum[C + ch], s1);        // label 1
            }
        }
    }

    // ---------------- Phase B: stream batches 0..6 (blocks 0..447) --------
    if (blk < 448) {
        int b    = blk >> 6;
        int slot = blk & 63;
        int p4   = slot * 256 + t;
        int n0   = p4 << 2;
        const float4* Fb = reinterpret_cast<const float4*>(F + (size_t)b * C * NPIX);

        float4 a0 = make_float4(0.f,0.f,0.f,0.f);
        float4 a1 = make_float4(0.f,0.f,0.f,0.f);
        #pragma unroll 8
        for (int ch = 0; ch < C; ch++) {
            float4 f = __ldcs(&Fb[ch * (NPIX/4) + p4]);
            float c0 = sc[ch], c1 = sc[C + ch];
            a0.x += f.x*c0; a0.y += f.y*c0; a0.z += f.z*c0; a0.w += f.w*c0;
            a1.x += f.x*c1; a1.y += f.y*c1; a1.z += f.z*c1; a1.w += f.w*c1;
        }

        float d0x = 0.5f - 0.5f*a0.x, d1x = 0.5f - 0.5f*a1.x;
        float d0y = 0.5f - 0.5f*a0.y, d1y = 0.5f - 0.5f*a1.y;
        float d0z = 0.5f - 0.5f*a0.z, d1z = 0.5f - 0.5f*a1.z;
        float d0w = 0.5f - 0.5f*a0.w, d1w = 0.5f - 0.5f*a1.w;

        int lx = d1x < d0x, ly = d1y < d0y, lz = d1z < d0z, lw = d1w < d0w;
        float4 lab = make_float4((float)lx, (float)ly, (float)lz, (float)lw);

        __stcs(reinterpret_cast<float4*>(out + OFF_LABELS + (size_t)b*NPIX + n0), lab);
        __stcs(reinterpret_cast<float4*>(out + OFF_LABELT + (size_t)b*NPIX + n0), lab);

        float4* outO = reinterpret_cast<float4*>(out + OFF_ONEHOT + (size_t)b*2*NPIX + 2*n0);
        __stcs(outO + 0, make_float4(1.f - lab.x, lab.x, 1.f - lab.y, lab.y));
        __stcs(outO + 1, make_float4(1.f - lab.z, lab.z, 1.f - lab.w, lab.w));

        float4* outD = reinterpret_cast<float4*>(out + OFF_DIST + (size_t)b*2*NPIX + 2*n0);
        __stcs(outD + 0, make_float4(d0x, d1x, d0y, d1y));
        __stcs(outD + 1, make_float4(d0z, d1z, d0w, d1w));
    }

    // ---------------- arrival; last block does the epilogue ---------------
    __syncthreads();
    if (t == 0) {
        __threadfence();
        int old = atomicAdd(&g_arrive, 1);
        s_done = (old == NBLK - 1);
    }
    __syncthreads();
    if (!s_done) return;
    __threadfence();

    float sum = g_sum[t];
    int   cnt = g_cnt;
    int k = t >> 7;
    float num = (k ? (float)cnt : (float)(NPIX - cnt)) + 1.0f;
    float mean = sum / num;
    float ci = sc[t];
    out[OFF_CENTERS + t] = ci + 0.001f * (mean - ci);

    // self-reset scratch for the next graph replay
    g_sum[t] = 0.0f;
    if (t == 0) { g_cnt = 0; g_arrive = 0; }
}

// ---------------------------------------------------------------------------
extern "C" void kernel_launch(void* const* d_in, const int* in_sizes, int n_in,
                              void* d_out, int out_size) {
    const float* F     = (const float*)d_in[0];   // FeatureT [8,128,256,256]
    const float* Cinit = (const float*)d_in[1];   // centerInit [2,128]
    float* out = (float*)d_out;
    (void)in_sizes; (void)n_in; (void)out_size;

    k_all<<<NBLK, 256>>>(F, Cinit, out);
}

// round 8
// speedup vs baseline: 2.1573x; 2.1573x over previous
#include <cuda_runtime.h>
#include <cstdint>

// Problem constants
#define BB    8
#define C     128
#define W     256
#define H     256
#define NPIX  (W*H)          // 65536 pixels per image
#define NBLK  512
#define NB7   64             // b7 tiles / slots
#define NTILE 448            // b0..6 tiles in the dynamic queue

// Output buffer layout (concatenated f32, raw reshapes):
#define OFF_CENTERS 0
#define OFF_LABELS  256
#define OFF_ONEHOT  (OFF_LABELS + BB*NPIX)
#define OFF_DIST    (OFF_ONEHOT + BB*2*NPIX)
#define OFF_LABELT  (OFF_DIST   + BB*2*NPIX)

// Scratch (__device__ globals; overwrite-slot semantics, counters self-reset).
__device__ float g_part[NB7 * 256];  // [slot*256 + (k*128+ch)] label-k ch sums
__device__ int   g_cntp[NB7];        // per-slot label==1 count
__device__ int   g_work  = 0;        // dynamic tile queue head (b0..6)
__device__ int   g_arrive = 0;       // terminal arrival counter

// ---------------------------------------------------------------------------
// Main-tile worker: dots vs both centers, labels, all big outputs.
// Returns label flags for caller (b7 path needs them).
// ---------------------------------------------------------------------------
template <bool STREAM>
__device__ __forceinline__ float4 main_tile(const float* __restrict__ F,
                                            const float* __restrict__ sc,
                                            float* __restrict__ out,
                                            int b, int p4) {
    int n0 = p4 << 2;
    const float4* Fb = reinterpret_cast<const float4*>(F + (size_t)b * C * NPIX);

    float4 a0 = make_float4(0.f,0.f,0.f,0.f);
    float4 a1 = make_float4(0.f,0.f,0.f,0.f);
    #pragma unroll 8
    for (int ch = 0; ch < C; ch++) {
        float4 f = STREAM ? __ldcs(&Fb[ch * (NPIX/4) + p4])
                          : Fb[ch * (NPIX/4) + p4];
        float c0 = sc[ch], c1 = sc[C + ch];
        a0.x += f.x*c0; a0.y += f.y*c0; a0.z += f.z*c0; a0.w += f.w*c0;
        a1.x += f.x*c1; a1.y += f.y*c1; a1.z += f.z*c1; a1.w += f.w*c1;
    }

    float d0x = 0.5f - 0.5f*a0.x, d1x = 0.5f - 0.5f*a1.x;
    float d0y = 0.5f - 0.5f*a0.y, d1y = 0.5f - 0.5f*a1.y;
    float d0z = 0.5f - 0.5f*a0.z, d1z = 0.5f - 0.5f*a1.z;
    float d0w = 0.5f - 0.5f*a0.w, d1w = 0.5f - 0.5f*a1.w;

    int lx = d1x < d0x, ly = d1y < d0y, lz = d1z < d0z, lw = d1w < d0w;
    float4 lab = make_float4((float)lx, (float)ly, (float)lz, (float)lw);

    __stcs(reinterpret_cast<float4*>(out + OFF_LABELS + (size_t)b*NPIX + n0), lab);
    __stcs(reinterpret_cast<float4*>(out + OFF_LABELT + (size_t)b*NPIX + n0), lab);

    float4* outO = reinterpret_cast<float4*>(out + OFF_ONEHOT + (size_t)b*2*NPIX + 2*n0);
    __stcs(outO + 0, make_float4(1.f - lab.x, lab.x, 1.f - lab.y, lab.y));
    __stcs(outO + 1, make_float4(1.f - lab.z, lab.z, 1.f - lab.w, lab.w));

    float4* outD = reinterpret_cast<float4*>(out + OFF_DIST + (size_t)b*2*NPIX + 2*n0);
    __stcs(outD + 0, make_float4(d0x, d1x, d0y, d1y));
    __stcs(outD + 1, make_float4(d0z, d1z, d0w, d1w));
    return lab;
}

// ---------------------------------------------------------------------------
// Single kernel, 512 blocks x 256 threads.
// Blocks 0..63  : b7 tile (default cache policy) -> local labels in smem ->
//                 immediate masked channel-sum re-read of OWN tile (L2-hot,
//                 no waiting) -> join the dynamic b0..6 queue.
// Blocks 64..511: dynamic queue of 448 b0..6 tiles (streaming policy).
// No block ever waits on another; the queue absorbs the b7 blocks' extra
// L2 pass. Last-arriving block does the epilogue + scratch reset.
// ---------------------------------------------------------------------------
__global__ void __launch_bounds__(256, 4)
k_all(const float* __restrict__ F,
      const float* __restrict__ Cinit,
      float* __restrict__ out) {
    __shared__ float  sc[2*C];
    __shared__ float4 slab[256];     // b7 blocks: labels for their 1024 pixels
    __shared__ int    wred[8];
    __shared__ int    s_done;

    int t    = threadIdx.x;
    int lane = t & 31;
    int wid  = t >> 5;
    int blk  = blockIdx.x;

    sc[t] = Cinit[t];
    __syncthreads();

    if (blk < NB7) {
        // ------------- b7 tile: phase 1 + local L2-hot phase 2 -------------
        int slot = blk;
        int p4   = slot * 256 + t;
        float4 lab = main_tile<false>(F, sc, out, BB - 1, p4);
        slab[t] = lab;

        // label-1 count for this tile
        {
            int s = (int)(lab.x + lab.y + lab.z + lab.w);
            #pragma unroll
            for (int o = 16; o > 0; o >>= 1)
                s += __shfl_down_sync(0xffffffffu, s, o);
            if (lane == 0) wred[wid] = s;
        }
        __syncthreads();
        if (t == 0) {
            int v = 0;
            #pragma unroll
            for (int i = 0; i < 8; i++) v += wred[i];
            g_cntp[slot] = v;
        }

        // masked channel sums over OWN 1024-pixel tile (just-read -> L2 hits)
        const float4* F7 = reinterpret_cast<const float4*>(
            F + (size_t)(BB-1) * C * NPIX);
        int base4 = slot * 256;
        #pragma unroll 2
        for (int j = 0; j < 16; j++) {
            int ch = wid + 8*j;
            const float4* row = F7 + (size_t)ch * (NPIX/4) + base4;
            float sa = 0.f, s1 = 0.f;
            #pragma unroll
            for (int i = 0; i < 8; i++) {
                float4 f = row[i*32 + lane];
                float4 l = slab[i*32 + lane];
                sa += f.x + f.y + f.z + f.w;
                s1 += f.x*l.x + f.y*l.y + f.z*l.z + f.w*l.w;
            }
            #pragma unroll
            for (int o = 16; o > 0; o >>= 1) {
                sa += __shfl_down_sync(0xffffffffu, sa, o);
                s1 += __shfl_down_sync(0xffffffffu, s1, o);
            }
            if (lane == 0) {
                g_part[slot*256 + ch]       = sa - s1;   // label 0
                g_part[slot*256 + 128 + ch] = s1;        // label 1
            }
        }
    }

    // ------------- dynamic queue over the 448 b0..6 tiles -------------
    __shared__ int s_tile;
    for (;;) {
        __syncthreads();
        if (t == 0) s_tile = atomicAdd(&g_work, 1);
        __syncthreads();
        int tile = s_tile;
        if (tile >= NTILE) break;
        int b    = tile >> 6;
        int slot = tile & 63;
        main_tile<true>(F, sc, out, b, slot * 256 + t);
    }

    // ------------- arrival; last block does the epilogue -------------
    if (t == 0) {
        __threadfence();
        int old = atomicAdd(&g_arrive, 1);
        s_done = (old == NBLK - 1);
    }
    __syncthreads();
    if (!s_done) return;
    __threadfence();

    // reduce 64 slots
    int cnt = 0;
    #pragma unroll 8
    for (int s = 0; s < NB7; s++) cnt += g_cntp[s];
    float sum = 0.f;
    #pragma unroll 8
    for (int s = 0; s < NB7; s++) sum += g_part[s*256 + t];

    int k = t >> 7;
    float num = (k ? (float)cnt : (float)(NPIX - cnt)) + 1.0f;
    float mean = sum / num;
    float ci = sc[t];
    out[OFF_CENTERS + t] = ci + 0.001f * (mean - ci);

    if (t == 0) { g_work = 0; g_arrive = 0; }   // reset for next graph replay
}

// ---------------------------------------------------------------------------
extern "C" void kernel_launch(void* const* d_in, const int* in_sizes, int n_in,
                              void* d_out, int out_size) {
    const float* F     = (const float*)d_in[0];   // FeatureT [8,128,256,256]
    const float* Cinit = (const float*)d_in[1];   // centerInit [2,128]
    float* out = (float*)d_out;
    (void)in_sizes; (void)n_in; (void)out_size;

    k_all<<<NBLK, 256>>>(F, Cinit, out);
}